// round 3
// baseline (speedup 1.0000x reference)
#include <cuda_runtime.h>
#include <math.h>

// ---------------- problem constants ----------------
#define NCAM 12          // B6
#define CIN 256
#define HID 256
#define FH 32
#define FW 88
#define HW (FH*FW)       // 2816
#define DBINS 41
#define CTXC 32
#define NB 2             // batch
#define BCIN 192         // 6*32
#define BEV 400
#define BMID 64
#define BEVHW (BEV*BEV)  // 160000

// ---------------- scratch (device globals; no allocations) ----------------
__device__ float g_hidden[2*NCAM*HID*FH*FW];         // both heads
__device__ float g_context[NCAM*CTXC*FH*FW];         // == (2,192,32,88) view
__device__ float g_bev[(size_t)NB*BCIN*BEV*BEV];     // 245.8 MB
__device__ float g_wt_d[CIN*9*HID];                  // dw1 transposed [ic][k][oc]
__device__ float g_wt_c[CIN*9*HID];                  // cw1 transposed
__device__ float g_wt_b[BCIN*9*BMID];                // bw1 transposed
__device__ float g_w2t[BMID*BMID];                   // bw2 transposed [i][o]

// ======================================================================
// Weight transposes: [oc][ic][3][3] -> [ic][k][oc]   (coalesced staging later)
// ======================================================================
__global__ void transpose_w(const float* __restrict__ w, float* __restrict__ o,
                            int OC, int IC)
{
    int idx = blockIdx.x*256 + threadIdx.x;
    if (idx >= OC*IC*9) return;
    int oc = idx / (IC*9);
    int r  = idx - oc*IC*9;
    int ic = r / 9;
    int k  = r - ic*9;
    o[(ic*9 + k)*OC + oc] = w[idx];
}

__global__ void transpose_w2(const float* __restrict__ w, float* __restrict__ o)
{
    int idx = threadIdx.x + blockIdx.x*256;  // 4096
    if (idx >= BMID*BMID) return;
    int oc = idx / BMID, ic = idx - oc*BMID;
    o[ic*BMID + oc] = w[idx];
}

// ======================================================================
// Head conv3x3 (256->256) + BN + ReLU, both heads (blockIdx.z).
// Block: (n, h, 64 oc, 88 w). blockDim (22,8): thread tile = 4w x 8oc.
// ======================================================================
#define ICB 8
#define INPAD 92   // FW+2 padded to 16B multiple

__global__ __launch_bounds__(176) void head_conv3(
    const float* __restrict__ feat,
    const float* __restrict__ bias_d, const float* __restrict__ gam_d,
    const float* __restrict__ bet_d,  const float* __restrict__ mu_d,
    const float* __restrict__ var_d,
    const float* __restrict__ bias_c, const float* __restrict__ gam_c,
    const float* __restrict__ bet_c,  const float* __restrict__ mu_c,
    const float* __restrict__ var_c)
{
    __shared__ __align__(16) float sm[3*ICB*INPAD + ICB*9*64];
    float* in_s = sm;                      // [3][ICB][INPAD]
    float* w_s  = sm + 3*ICB*INPAD;        // [ICB][9][64]

    const int head = blockIdx.z;
    const float* wt   = head ? g_wt_c : g_wt_d;
    const float* bias = head ? bias_c : bias_d;
    const float* gam  = head ? gam_c  : gam_d;
    const float* bet  = head ? bet_c  : bet_d;
    const float* mu   = head ? mu_c   : mu_d;
    const float* var  = head ? var_c  : var_d;
    float* dst = g_hidden + (size_t)head*NCAM*HID*HW;

    const int n   = blockIdx.x / FH;
    const int h   = blockIdx.x % FH;
    const int oc0 = blockIdx.y * 64;
    const int tx  = threadIdx.x;           // 0..21 -> w tile of 4
    const int ty  = threadIdx.y;           // 0..7  -> oc group of 8
    const int tid = ty*22 + tx;

    float acc[8][4];
#pragma unroll
    for (int j = 0; j < 8; j++)
#pragma unroll
        for (int wi = 0; wi < 4; wi++) acc[j][wi] = 0.f;

    for (int ic0 = 0; ic0 < CIN; ic0 += ICB) {
        // stage input rows h-1..h+1 (halo) for ICB channels
        for (int idx = tid; idx < 3*ICB*(FW+2); idx += 176) {
            int dy = idx / (ICB*(FW+2));
            int r  = idx - dy*ICB*(FW+2);
            int ic = r / (FW+2);
            int wl = r - ic*(FW+2);
            int hh = h - 1 + dy, ww = wl - 1;
            float v = 0.f;
            if (hh >= 0 && hh < FH && ww >= 0 && ww < FW)
                v = feat[((n*CIN + ic0+ic)*FH + hh)*FW + ww];
            in_s[(dy*ICB + ic)*INPAD + wl] = v;
        }
        // stage weights (coalesced from transposed layout)
        for (int idx = tid; idx < ICB*9*64; idx += 176) {
            int ic  = idx / 576;
            int r   = idx - ic*576;
            int k   = r / 64;
            int ocl = r - k*64;
            w_s[(ic*9 + k)*64 + ocl] = wt[((ic0+ic)*9 + k)*HID + oc0 + ocl];
        }
        __syncthreads();

#pragma unroll
        for (int ic = 0; ic < ICB; ic++) {
#pragma unroll
            for (int dy = 0; dy < 3; dy++) {
                const float* row = &in_s[(dy*ICB + ic)*INPAD + tx*4];
                float4 a = *reinterpret_cast<const float4*>(row);
                float2 b = *reinterpret_cast<const float2*>(row + 4);
                float iv[6] = {a.x, a.y, a.z, a.w, b.x, b.y};
#pragma unroll
                for (int dx = 0; dx < 3; dx++) {
                    const float* wrow = &w_s[(ic*9 + dy*3 + dx)*64 + ty*8];
                    float4 w0 = *reinterpret_cast<const float4*>(wrow);
                    float4 w1 = *reinterpret_cast<const float4*>(wrow + 4);
                    float wv[8] = {w0.x,w0.y,w0.z,w0.w,w1.x,w1.y,w1.z,w1.w};
#pragma unroll
                    for (int j = 0; j < 8; j++)
#pragma unroll
                        for (int wi = 0; wi < 4; wi++)
                            acc[j][wi] = fmaf(wv[j], iv[wi+dx], acc[j][wi]);
                }
            }
        }
        __syncthreads();
    }

    // fused conv-bias + BN + ReLU epilogue
#pragma unroll
    for (int j = 0; j < 8; j++) {
        int oc = oc0 + ty*8 + j;
        float s = gam[oc] * rsqrtf(var[oc] + 1e-5f);
        float t = bet[oc] + (bias[oc] - mu[oc]) * s;
        float4 o;
        float* v = &o.x;
#pragma unroll
        for (int wi = 0; wi < 4; wi++)
            v[wi] = fmaxf(fmaf(acc[j][wi], s, t), 0.f);
        *reinterpret_cast<float4*>(&dst[((n*HID + oc)*FH + h)*FW + tx*4]) = o;
    }
}

// ======================================================================
// Head conv1x1 (256 -> Cout), both heads, parallel over pixels.
// grid (11, 6, 24): pixel chunk x oc-group x (head*NCAM+n)
// ======================================================================
__global__ __launch_bounds__(256) void head_conv1(
    const float* __restrict__ dw2, const float* __restrict__ db2,
    const float* __restrict__ cw2, const float* __restrict__ cb2,
    float* __restrict__ depth_out)
{
    const int head = blockIdx.z >= NCAM;
    const int n    = blockIdx.z - head*NCAM;
    if (head && blockIdx.y >= 4) return;   // ctx has 32 oc = 4 groups

    const int Cout = head ? CTXC : DBINS;
    const float* w = head ? cw2 : dw2;
    const float* b = head ? cb2 : db2;
    const float* src = g_hidden + (size_t)head*NCAM*HID*HW + (size_t)n*HID*HW;
    float* dst = head ? (g_context + (size_t)n*CTXC*HW) : (depth_out + (size_t)n*DBINS*HW);

    const int o0 = blockIdx.y * 8;
    const int OB = (Cout - o0 < 8) ? (Cout - o0) : 8;
    const int tid = threadIdx.x;
    const int p = blockIdx.x*256 + tid;    // HW = 11*256 exactly

    __shared__ float ws[8][CIN];
    for (int idx = tid; idx < OB*CIN; idx += 256) {
        int j = idx / CIN, ic = idx - j*CIN;
        ws[j][ic] = w[(o0+j)*CIN + ic];
    }
    __syncthreads();

    float acc[8];
#pragma unroll
    for (int j = 0; j < 8; j++) acc[j] = 0.f;
#pragma unroll 8
    for (int ic = 0; ic < CIN; ic++) {
        float v = src[ic*HW + p];
#pragma unroll
        for (int j = 0; j < 8; j++) acc[j] = fmaf(v, ws[j][ic], acc[j]);
    }
#pragma unroll
    for (int j = 0; j < 8; j++)
        if (j < OB) dst[(o0+j)*HW + p] = acc[j] + b[o0+j];
}

// ======================================================================
// Bilinear resize (half-pixel centers, clamp): (2,192,32,88)->(2,192,400,400)
// float4 stores (BEV = 400 = 100*4)
// ======================================================================
__global__ __launch_bounds__(256) void upsample_k()
{
    long idx = (long)blockIdx.x * 256 + threadIdx.x;
    const long total = (long)NB*BCIN*BEV*100;
    if (idx >= total) return;
    int q = (int)(idx % 100);
    long r = idx / 100;
    int i = (int)(r % BEV);  r /= BEV;
    int g = (int)(r % BCIN);
    int b = (int)(r / BCIN);

    float sy = (i + 0.5f) * (32.f/400.f) - 0.5f;
    int y0 = (int)floorf(sy); float fy = sy - (float)y0;
    int y1 = y0 + 1;
    y0 = max(0, min(FH-1, y0)); y1 = max(0, min(FH-1, y1));
    const float* p0 = g_context + ((long)b*BCIN + g)*HW + y0*FW;
    const float* p1 = g_context + ((long)b*BCIN + g)*HW + y1*FW;

    float4 o;
    float* ov = &o.x;
#pragma unroll
    for (int c = 0; c < 4; c++) {
        int j = q*4 + c;
        float sx = (j + 0.5f) * (88.f/400.f) - 0.5f;
        int x0 = (int)floorf(sx); float fx = sx - (float)x0;
        int x1 = x0 + 1;
        x0 = max(0, min(FW-1, x0)); x1 = max(0, min(FW-1, x1));
        float t = p0[x0] + (p0[x1] - p0[x0]) * fx;
        float bo = p1[x0] + (p1[x1] - p1[x0]) * fx;
        ov[c] = t + (bo - t) * fy;
    }
    *reinterpret_cast<float4*>(&g_bev[(((long)b*BCIN + g)*BEV + i)*BEV + q*4]) = o;
}

// ======================================================================
// BEV conv3x3 (192->64) + GELU + conv1x1 (64->64), fully fused.
// Block covers (b, h, 64 w, all oc). blockDim (16,16): tile 4w x 4oc.
// ======================================================================
#define BICB 12
#define BINPAD 68

__global__ __launch_bounds__(256) void bev_fused(
    const float* __restrict__ bb1, const float* __restrict__ bb2,
    float* __restrict__ out)
{
    __shared__ __align__(16) float sm[3*BICB*BINPAD + BICB*9*64]; // 9360 floats
    float* in_s = sm;                         // [3][BICB][BINPAD]
    float* w_s  = sm + 3*BICB*BINPAD;         // [BICB][9][64]
    // phase-2 overlay
    float* s_ex = sm;                         // [64][68]
    float* w2s  = sm + 64*68;                 // [64][64]
    float* b2s  = sm + 64*68 + 64*64;         // [64]

    const int wblk = blockIdx.x * 64;
    const int h    = blockIdx.y;
    const int b    = blockIdx.z;
    const int tx   = threadIdx.x;             // 0..15 -> w tile of 4
    const int ty   = threadIdx.y;             // 0..15 -> oc group of 4
    const int tid  = ty*16 + tx;

    float acc[4][4];
#pragma unroll
    for (int j = 0; j < 4; j++)
#pragma unroll
        for (int wi = 0; wi < 4; wi++) acc[j][wi] = 0.f;

    for (int ic0 = 0; ic0 < BCIN; ic0 += BICB) {
        for (int idx = tid; idx < 3*BICB*66; idx += 256) {
            int dy = idx / (BICB*66);
            int r  = idx - dy*BICB*66;
            int ic = r / 66;
            int wl = r - ic*66;
            int hh = h - 1 + dy, ww = wblk + wl - 1;
            float v = 0.f;
            if (hh >= 0 && hh < BEV && ww >= 0 && ww < BEV)
                v = g_bev[(((long)b*BCIN + ic0+ic)*BEV + hh)*BEV + ww];
            in_s[(dy*BICB + ic)*BINPAD + wl] = v;
        }
        for (int idx = tid; idx < BICB*9*64; idx += 256) {
            int ic  = idx / 576;
            int r   = idx - ic*576;
            int k   = r / 64;
            int ocl = r - k*64;
            w_s[(ic*9 + k)*64 + ocl] = g_wt_b[((ic0+ic)*9 + k)*BMID + ocl];
        }
        __syncthreads();

#pragma unroll
        for (int ic = 0; ic < BICB; ic++) {
#pragma unroll
            for (int dy = 0; dy < 3; dy++) {
                const float* row = &in_s[(dy*BICB + ic)*BINPAD + tx*4];
                float4 a = *reinterpret_cast<const float4*>(row);
                float2 b2v = *reinterpret_cast<const float2*>(row + 4);
                float iv[6] = {a.x, a.y, a.z, a.w, b2v.x, b2v.y};
#pragma unroll
                for (int dx = 0; dx < 3; dx++) {
                    float4 w0 = *reinterpret_cast<const float4*>(
                        &w_s[(ic*9 + dy*3 + dx)*64 + ty*4]);
                    float wv[4] = {w0.x, w0.y, w0.z, w0.w};
#pragma unroll
                    for (int j = 0; j < 4; j++)
#pragma unroll
                        for (int wi = 0; wi < 4; wi++)
                            acc[j][wi] = fmaf(wv[j], iv[wi+dx], acc[j][wi]);
                }
            }
        }
        __syncthreads();
    }

    // ---- phase 2: GELU -> smem exchange -> 1x1 (64->64) -> gmem ----
    __syncthreads();   // everyone done reading in_s/w_s

    {
        // write GELU(conv+bias) to s_ex[oc][w_local]
#pragma unroll
        for (int j = 0; j < 4; j++) {
            int oc = ty*4 + j;
            float bv = bb1[oc];
#pragma unroll
            for (int wi = 0; wi < 4; wi++) {
                float x = acc[j][wi] + bv;
                s_ex[oc*BINPAD + tx*4 + wi] =
                    0.5f * x * (1.f + erff(x * 0.70710678118654752f));
            }
        }
        // stage transposed 1x1 weights + bias
        for (int idx = tid; idx < BMID*BMID; idx += 256)
            w2s[idx] = g_w2t[idx];
        if (tid < BMID) b2s[tid] = bb2[tid];
    }
    __syncthreads();

    float acc2[4][4];
#pragma unroll
    for (int j = 0; j < 4; j++)
#pragma unroll
        for (int wi = 0; wi < 4; wi++) acc2[j][wi] = b2s[ty*4 + j];

#pragma unroll 8
    for (int i = 0; i < BMID; i++) {
        float4 sv = *reinterpret_cast<const float4*>(&s_ex[i*BINPAD + tx*4]);
        float4 wv = *reinterpret_cast<const float4*>(&w2s[i*BMID + ty*4]);
        float svv[4] = {sv.x, sv.y, sv.z, sv.w};
        float wvv[4] = {wv.x, wv.y, wv.z, wv.w};
#pragma unroll
        for (int j = 0; j < 4; j++)
#pragma unroll
            for (int wi = 0; wi < 4; wi++)
                acc2[j][wi] = fmaf(wvv[j], svv[wi], acc2[j][wi]);
    }

    const int wbase = wblk + tx*4;
    if (wbase + 3 < BEV) {
#pragma unroll
        for (int j = 0; j < 4; j++) {
            int oc = ty*4 + j;
            float4 o = {acc2[j][0], acc2[j][1], acc2[j][2], acc2[j][3]};
            *reinterpret_cast<float4*>(
                &out[(((long)b*BMID + oc)*BEV + h)*BEV + wbase]) = o;
        }
    } else {
#pragma unroll
        for (int j = 0; j < 4; j++) {
            int oc = ty*4 + j;
#pragma unroll
            for (int wi = 0; wi < 4; wi++)
                if (wbase + wi < BEV)
                    out[(((long)b*BMID + oc)*BEV + h)*BEV + wbase + wi] = acc2[j][wi];
        }
    }
}

// ======================================================================
extern "C" void kernel_launch(void* const* d_in, const int* in_sizes, int n_in,
                              void* d_out, int out_size)
{
    const float* feat   = (const float*)d_in[0];
    const float* dw1    = (const float*)d_in[1];
    const float* db1    = (const float*)d_in[2];
    const float* dgamma = (const float*)d_in[3];
    const float* dbeta  = (const float*)d_in[4];
    const float* dmean  = (const float*)d_in[5];
    const float* dvar   = (const float*)d_in[6];
    const float* dw2    = (const float*)d_in[7];
    const float* db2    = (const float*)d_in[8];
    const float* cw1    = (const float*)d_in[9];
    const float* cb1    = (const float*)d_in[10];
    const float* cgamma = (const float*)d_in[11];
    const float* cbeta  = (const float*)d_in[12];
    const float* cmean  = (const float*)d_in[13];
    const float* cvar   = (const float*)d_in[14];
    const float* cw2    = (const float*)d_in[15];
    const float* cb2    = (const float*)d_in[16];
    const float* bw1    = (const float*)d_in[17];
    const float* bb1    = (const float*)d_in[18];
    const float* bw2    = (const float*)d_in[19];
    const float* bb2    = (const float*)d_in[20];

    float* out = (float*)d_out;
    float* depth_logits = out + (long)NB*BMID*BEVHW;   // (12,41,32,88)

    float *p_wt_d, *p_wt_c, *p_wt_b, *p_w2t;
    cudaGetSymbolAddress((void**)&p_wt_d, g_wt_d);
    cudaGetSymbolAddress((void**)&p_wt_c, g_wt_c);
    cudaGetSymbolAddress((void**)&p_wt_b, g_wt_b);
    cudaGetSymbolAddress((void**)&p_w2t,  g_w2t);

    // weight preprocessing (coalesced staging layouts)
    transpose_w<<<(HID*CIN*9 + 255)/256, 256>>>(dw1, p_wt_d, HID, CIN);
    transpose_w<<<(HID*CIN*9 + 255)/256, 256>>>(cw1, p_wt_c, HID, CIN);
    transpose_w<<<(BMID*BCIN*9 + 255)/256, 256>>>(bw1, p_wt_b, BMID, BCIN);
    transpose_w2<<<(BMID*BMID + 255)/256, 256>>>(bw2, p_w2t);

    // both head conv3x3 (+BN+ReLU) in one launch
    head_conv3<<<dim3(NCAM*FH, 4, 2), dim3(22, 8)>>>(
        feat, db1, dgamma, dbeta, dmean, dvar,
              cb1, cgamma, cbeta, cmean, cvar);

    // both head 1x1 convs (softmax-sum == 1, so pooled == context)
    head_conv1<<<dim3(11, 6, 2*NCAM), 256>>>(dw2, db2, cw2, cb2, depth_logits);

    // bilinear upsample (reshape is a pure view of g_context)
    {
        long total = (long)NB*BCIN*BEV*100;
        upsample_k<<<(int)((total + 255)/256), 256>>>();
    }

    // bev conv3x3 + GELU + 1x1 fused
    bev_fused<<<dim3(7, BEV, NB), dim3(16, 16)>>>(bb1, bb2, out);
}

// round 6
// speedup vs baseline: 2.6354x; 2.6354x over previous
#include <cuda_runtime.h>
#include <stdint.h>
#include <math.h>

#define NCAM 12
#define CIN 256
#define FH 32
#define FW 88
#define HW 2816
#define DBINS 41
#define CTXC 32
#define NB 2
#define BCIN 192
#define BEV 400
#define BMID 64
#define BEVHW 160000

// ---------------- scratch (device globals; no allocations) ----------------
// weight fragment arrays: [k8][fn][lane]{b0,b1}
__device__ __align__(16) float g_w1d[288*32*32*2];   // head depth conv3x3, K=2304, N=256
__device__ __align__(16) float g_w1c[288*32*32*2];   // head ctx conv3x3
__device__ __align__(16) float g_w1b[216*8*32*2];    // bev conv3x3, K=1728, N=64
__device__ __align__(16) float g_w2d[32*8*32*2];     // depth 1x1, K=256, N=64(pad 41)
__device__ __align__(16) float g_w2c[32*8*32*2];     // ctx 1x1, K=256, N=64(pad 32)
__device__ __align__(16) float g_w2b[8*8*32*2];      // bev 1x1, K=64, N=64
// hidden activations in A-fragment order: [head][n][pb][k8*8+fm][lane][4]
__device__ __align__(16) float g_hidA[(size_t)2*NCAM*22*128*256];
__device__ __align__(16) float g_context[NCAM*CTXC*HW];
__device__ __align__(16) float g_bev[(size_t)NB*BCIN*BEVHW];

// ---------------- helpers ----------------
// cvt.rna.tf32.f32 requires a .b32 destination register
__device__ __forceinline__ uint32_t f2tf32(float x){
    uint32_t r; asm("cvt.rna.tf32.f32 %0, %1;" : "=r"(r) : "f"(x)); return r;
}
__device__ __forceinline__ float to_tf32(float x){
    return __uint_as_float(f2tf32(x));
}
__device__ __forceinline__ void mma8(float4& d,
    uint32_t a0, uint32_t a1, uint32_t a2, uint32_t a3,
    uint32_t b0, uint32_t b1)
{
    asm volatile("mma.sync.aligned.m16n8k8.row.col.f32.tf32.tf32.f32 "
        "{%0,%1,%2,%3}, {%4,%5,%6,%7}, {%8,%9}, {%0,%1,%2,%3};"
        : "+f"(d.x), "+f"(d.y), "+f"(d.z), "+f"(d.w)
        : "r"(a0), "r"(a1), "r"(a2), "r"(a3), "r"(b0), "r"(b1));
}

// ============ weight prep: conv w[OC][IC][3][3] -> B-fragment order ============
// k = t*IC + ic (tap-major). out[((k8*NF+fn)*32 + l)*2 + pos], l = (oc&7)*4+(k&3), pos=(k&7)>>2
__global__ void prep_w1frag(const float* __restrict__ w, float* __restrict__ o,
                            int OC, int IC)
{
    int idx = blockIdx.x*256 + threadIdx.x;
    if (idx >= OC*IC*9) return;
    int oc = idx / (IC*9);
    int rr = idx - oc*(IC*9);
    int ic = rr / 9;
    int t  = rr - ic*9;
    int k  = t*IC + ic;
    int NF = OC >> 3;
    int l = (oc & 7)*4 + (k & 3);
    int pos = (k & 7) >> 2;
    o[(((k>>3)*NF + (oc>>3))*32 + l)*2 + pos] = to_tf32(w[idx]);
}
// 1x1 w[OC][K] -> frags padded to 64 rows
__global__ void prep_w2frag(const float* __restrict__ w, float* __restrict__ o,
                            int OC, int K)
{
    int idx = blockIdx.x*256 + threadIdx.x;
    if (idx >= 64*K) return;
    int oc = idx / K, k = idx - oc*K;
    float v = (oc < OC) ? to_tf32(w[(size_t)oc*K + k]) : 0.f;
    int l = (oc & 7)*4 + (k & 3);
    int pos = (k & 7) >> 2;
    o[(((k>>3)*8 + (oc>>3))*32 + l)*2 + pos] = v;
}

// ============ HEAD conv3x3 + BN + ReLU -> g_hidA (frag order) ============
// grid (22, 12, 2), 512 threads. M=128 px, N=256, K=2304 (72 chunks of 32).
__global__ __launch_bounds__(512) void head3_mma(
    const float* __restrict__ feat,
    const float* __restrict__ db1, const float* __restrict__ dg,
    const float* __restrict__ dbt, const float* __restrict__ dm, const float* __restrict__ dv,
    const float* __restrict__ cb1, const float* __restrict__ cg,
    const float* __restrict__ cbt, const float* __restrict__ cm, const float* __restrict__ cv)
{
    __shared__ __align__(16) float Abuf[2][4096];
    __shared__ float sS[256], sT[256];

    const int tid = threadIdx.x;
    const int pb = blockIdx.x, n = blockIdx.y, head = blockIdx.z;
    const float* W1 = head ? g_w1c : g_w1d;

    if (tid < 256){
        int c = tid;
        float gam = head ? cg[c]  : dg[c];
        float var = head ? cv[c]  : dv[c];
        float bet = head ? cbt[c] : dbt[c];
        float mu  = head ? cm[c]  : dm[c];
        float bi  = head ? cb1[c] : db1[c];
        float s = gam * rsqrtf(var + 1e-5f);
        sS[c] = s;
        sT[c] = bet + (bi - mu)*s;
    }

    const int lane = tid & 31;
    const int wrp  = tid >> 5;
    const int wm = wrp & 3;          // m-warp (covers fm = wm*2, wm*2+1)
    const int wn = wrp >> 2;         // n-warp (covers fn = wn*8 .. +7)

    // staging precompute: 2 slots per thread
    int sH0[2], sW0[2], sH1[2], sW1[2], sOff0[2], sOff1[2], sIc[2], sSlot[2];
#pragma unroll
    for (int i = 0; i < 2; i++){
        int s = tid + i*512;         // 0..1023
        int fm = s >> 7, fk = (s >> 5) & 3, l = s & 31;
        int m0 = fm*16 + (l >> 2);
        int px0 = pb*128 + m0, px1 = px0 + 8;
        sH0[i] = px0 / FW; sW0[i] = px0 % FW;
        sH1[i] = px1 / FW; sW1[i] = px1 % FW;
        sOff0[i] = px0; sOff1[i] = px1;
        sIc[i] = fk*8 + (l & 3);
        sSlot[i] = s;
    }

    float4 acc[2][8];
#pragma unroll
    for (int mi = 0; mi < 2; mi++)
#pragma unroll
        for (int j = 0; j < 8; j++) acc[mi][j] = make_float4(0.f,0.f,0.f,0.f);

    float pv[2][4];
    // gather chunk ch into pv
    auto gather = [&](int ch){
        int t = ch >> 3, icb = ch & 7;
        int dy = t/3 - 1, dx = t - (t/3)*3 - 1;
#pragma unroll
        for (int i = 0; i < 2; i++){
            int ic = icb*32 + sIc[i];
            const float* base = feat + ((size_t)n*CIN + ic)*HW;
            bool ok0 = (unsigned)(sH0[i]+dy) < FH && (unsigned)(sW0[i]+dx) < FW;
            bool ok1 = (unsigned)(sH1[i]+dy) < FH && (unsigned)(sW1[i]+dx) < FW;
            int o0 = sOff0[i] + dy*FW + dx;
            int o1 = sOff1[i] + dy*FW + dx;
            pv[i][0] = ok0 ? to_tf32(__ldg(base + o0)) : 0.f;
            pv[i][1] = ok1 ? to_tf32(__ldg(base + o1)) : 0.f;
            pv[i][2] = ok0 ? to_tf32(__ldg(base + 4*HW + o0)) : 0.f;
            pv[i][3] = ok1 ? to_tf32(__ldg(base + 4*HW + o1)) : 0.f;
        }
    };
    auto store_stage = [&](int buf){
#pragma unroll
        for (int i = 0; i < 2; i++)
            *reinterpret_cast<float4*>(&Abuf[buf][sSlot[i]*4]) =
                make_float4(pv[i][0], pv[i][1], pv[i][2], pv[i][3]);
    };

    gather(0);
    store_stage(0);
    __syncthreads();

    for (int ch = 0; ch < 72; ch++){
        if (ch < 71) gather(ch + 1);
        const float4* Af = reinterpret_cast<const float4*>(&Abuf[ch & 1][0]);
        const float2* Bbase = reinterpret_cast<const float2*>(W1);
#pragma unroll
        for (int fk = 0; fk < 4; fk++){
            int k8g = ch*4 + fk;
            uint32_t a[2][4];
#pragma unroll
            for (int mi = 0; mi < 2; mi++){
                float4 av = Af[((wm*2 + mi)*4 + fk)*32 + lane];
                a[mi][0] = __float_as_uint(av.x); a[mi][1] = __float_as_uint(av.y);
                a[mi][2] = __float_as_uint(av.z); a[mi][3] = __float_as_uint(av.w);
            }
            const float2* Bf = Bbase + (size_t)k8g*32*32 + lane;
#pragma unroll
            for (int j = 0; j < 8; j++){
                float2 bv = __ldg(Bf + (wn*8 + j)*32);
                uint32_t b0 = __float_as_uint(bv.x), b1 = __float_as_uint(bv.y);
                mma8(acc[0][j], a[0][0],a[0][1],a[0][2],a[0][3], b0,b1);
                mma8(acc[1][j], a[1][0],a[1][1],a[1][2],a[1][3], b0,b1);
            }
        }
        if (ch < 71) store_stage((ch + 1) & 1);
        __syncthreads();
    }

    // epilogue: BN + ReLU, write in stage-2 A-fragment order
    const int g4 = lane >> 2, t4 = lane & 3;
    float* dst = g_hidA + ((size_t)(head*NCAM + n)*22 + pb)*32768;
#pragma unroll
    for (int mi = 0; mi < 2; mi++){
        int fm = wm*2 + mi;
#pragma unroll
        for (int j = 0; j < 8; j++){
            int fn = wn*8 + j;
            float v[4] = {acc[mi][j].x, acc[mi][j].y, acc[mi][j].z, acc[mi][j].w};
#pragma unroll
            for (int q = 0; q < 4; q++){
                int oc = fn*8 + 2*t4 + (q & 1);
                int r2 = g4 + (q >> 1)*8;
                float val = fmaxf(fmaf(v[q], sS[oc], sT[oc]), 0.f);
                int l2  = g4*4 + (oc & 3);
                int pos = (r2 >> 3) + 2*((oc & 7) >> 2);
                dst[(size_t)((fn*8 + fm)*32 + l2)*4 + pos] = to_tf32(val);
            }
        }
    }
}

// ============ HEAD 1x1 (256 -> 41/32), reads g_hidA frags directly ============
// grid (22, 12, 2), 256 threads. M=128, N=64, K=256.
__global__ __launch_bounds__(256) void head1_mma(
    const float* __restrict__ db2, const float* __restrict__ cb2,
    float* __restrict__ depth_out)
{
    const int tid = threadIdx.x;
    const int pb = blockIdx.x, n = blockIdx.y, head = blockIdx.z;
    const int lane = tid & 31, wrp = tid >> 5;
    const int wm = wrp & 3, wn = wrp >> 2;     // 4m x 2n

    const float* W2 = head ? g_w2c : g_w2d;
    const float* Ab = g_hidA + ((size_t)(head*NCAM + n)*22 + pb)*32768;

    float4 acc[2][4];
#pragma unroll
    for (int mi = 0; mi < 2; mi++)
#pragma unroll
        for (int j = 0; j < 4; j++) acc[mi][j] = make_float4(0.f,0.f,0.f,0.f);

#pragma unroll 4
    for (int k8 = 0; k8 < 32; k8++){
        uint32_t a[2][4];
#pragma unroll
        for (int mi = 0; mi < 2; mi++){
            float4 av = __ldg(reinterpret_cast<const float4*>(Ab) +
                              (k8*8 + wm*2 + mi)*32 + lane);
            a[mi][0] = __float_as_uint(av.x); a[mi][1] = __float_as_uint(av.y);
            a[mi][2] = __float_as_uint(av.z); a[mi][3] = __float_as_uint(av.w);
        }
        const float2* Bf = reinterpret_cast<const float2*>(W2) + (size_t)k8*8*32 + lane;
#pragma unroll
        for (int j = 0; j < 4; j++){
            float2 bv = __ldg(Bf + (wn*4 + j)*32);
            uint32_t b0 = __float_as_uint(bv.x), b1 = __float_as_uint(bv.y);
            mma8(acc[0][j], a[0][0],a[0][1],a[0][2],a[0][3], b0,b1);
            mma8(acc[1][j], a[1][0],a[1][1],a[1][2],a[1][3], b0,b1);
        }
    }

    const int g4 = lane >> 2, t4 = lane & 3;
#pragma unroll
    for (int mi = 0; mi < 2; mi++){
        int fm = wm*2 + mi;
#pragma unroll
        for (int j = 0; j < 4; j++){
            int fn = wn*4 + j;
            float v[4] = {acc[mi][j].x, acc[mi][j].y, acc[mi][j].z, acc[mi][j].w};
#pragma unroll
            for (int q = 0; q < 4; q++){
                int oc = fn*8 + 2*t4 + (q & 1);
                int px = pb*128 + fm*16 + g4 + (q >> 1)*8;
                if (head == 0){
                    if (oc < DBINS)
                        depth_out[((size_t)n*DBINS + oc)*HW + px] = v[q] + __ldg(db2 + oc);
                } else {
                    if (oc < CTXC)
                        g_context[((size_t)n*CTXC + oc)*HW + px] = v[q] + __ldg(cb2 + oc);
                }
            }
        }
    }
}

// ============ bilinear upsample (half-pixel, clamp) ============
__global__ __launch_bounds__(256) void upsample_k()
{
    long idx = (long)blockIdx.x * 256 + threadIdx.x;
    const long total = (long)NB*BCIN*BEV*100;
    if (idx >= total) return;
    int q = (int)(idx % 100);
    long rr = idx / 100;
    int i = (int)(rr % BEV);  rr /= BEV;
    int g = (int)(rr % BCIN);
    int b = (int)(rr / BCIN);

    float sy = (i + 0.5f) * (32.f/400.f) - 0.5f;
    int y0 = (int)floorf(sy); float fy = sy - (float)y0;
    int y1 = y0 + 1;
    y0 = max(0, min(FH-1, y0)); y1 = max(0, min(FH-1, y1));
    const float* p0 = g_context + ((long)b*BCIN + g)*HW + y0*FW;
    const float* p1 = g_context + ((long)b*BCIN + g)*HW + y1*FW;

    float4 o; float* ov = &o.x;
#pragma unroll
    for (int c = 0; c < 4; c++){
        int j = q*4 + c;
        float sx = (j + 0.5f) * (88.f/400.f) - 0.5f;
        int x0 = (int)floorf(sx); float fx = sx - (float)x0;
        int x1 = x0 + 1;
        x0 = max(0, min(FW-1, x0)); x1 = max(0, min(FW-1, x1));
        float t  = p0[x0] + (p0[x1] - p0[x0]) * fx;
        float bo = p1[x0] + (p1[x1] - p1[x0]) * fx;
        ov[c] = t + (bo - t) * fy;
    }
    *reinterpret_cast<float4*>(&g_bev[(((long)b*BCIN + g)*BEV + i)*BEV + q*4]) = o;
}

// ============ BEV conv3x3 + GELU + 1x1, fused mma ============
// grid (13, 100, 2), 256 threads. Tile = 4 rows x 32 cols = 128 px. N=64, K=1728.
__global__ __launch_bounds__(256) void bev_mma(
    const float* __restrict__ bb1, const float* __restrict__ bb2,
    float* __restrict__ out)
{
    __shared__ __align__(16) float Abuf[2][4096];   // also A2 exchange (8192 floats)

    const int tid = threadIdx.x;
    const int wb = blockIdx.x, hb = blockIdx.y, b = blockIdx.z;
    const int lane = tid & 31, wrp = tid >> 5;
    const int wm = wrp & 3, wn = wrp >> 2;          // 4m x 2n

    // staging precompute: 4 slots per thread
    int sH0[4], sW0[4], sH1[4], sW1[4], sIc[4], sSlot[4];
#pragma unroll
    for (int i = 0; i < 4; i++){
        int s = tid + i*256;
        int fm = s >> 7, fk = (s >> 5) & 3, l = s & 31;
        int m0 = fm*16 + (l >> 2), m1 = m0 + 8;
        sH0[i] = hb*4 + (m0 >> 5); sW0[i] = wb*32 + (m0 & 31);
        sH1[i] = hb*4 + (m1 >> 5); sW1[i] = wb*32 + (m1 & 31);
        sIc[i] = fk*8 + (l & 3);
        sSlot[i] = s;
    }

    float4 acc[2][4];
#pragma unroll
    for (int mi = 0; mi < 2; mi++)
#pragma unroll
        for (int j = 0; j < 4; j++) acc[mi][j] = make_float4(0.f,0.f,0.f,0.f);

    float pv[4][4];
    auto gather = [&](int ch){
        int t = ch / 6, icb = ch - t*6;
        int dy = t/3 - 1, dx = t - (t/3)*3 - 1;
#pragma unroll
        for (int i = 0; i < 4; i++){
            int ic = icb*32 + sIc[i];
            const float* base = g_bev + ((size_t)b*BCIN + ic)*BEVHW;
            int h0 = sH0[i] + dy, w0 = sW0[i] + dx;
            int h1 = sH1[i] + dy, w1 = sW1[i] + dx;
            bool ok0 = (unsigned)h0 < BEV && (unsigned)w0 < BEV;
            bool ok1 = (unsigned)h1 < BEV && (unsigned)w1 < BEV;
            int o0 = h0*BEV + w0, o1 = h1*BEV + w1;
            pv[i][0] = ok0 ? to_tf32(__ldg(base + o0)) : 0.f;
            pv[i][1] = ok1 ? to_tf32(__ldg(base + o1)) : 0.f;
            pv[i][2] = ok0 ? to_tf32(__ldg(base + 4*BEVHW + o0)) : 0.f;
            pv[i][3] = ok1 ? to_tf32(__ldg(base + 4*BEVHW + o1)) : 0.f;
        }
    };
    auto store_stage = [&](int buf){
#pragma unroll
        for (int i = 0; i < 4; i++)
            *reinterpret_cast<float4*>(&Abuf[buf][sSlot[i]*4]) =
                make_float4(pv[i][0], pv[i][1], pv[i][2], pv[i][3]);
    };

    gather(0);
    store_stage(0);
    __syncthreads();

    for (int ch = 0; ch < 54; ch++){
        if (ch < 53) gather(ch + 1);
        const float4* Af = reinterpret_cast<const float4*>(&Abuf[ch & 1][0]);
        const float2* Bbase = reinterpret_cast<const float2*>(g_w1b);
#pragma unroll
        for (int fk = 0; fk < 4; fk++){
            int k8g = ch*4 + fk;
            uint32_t a[2][4];
#pragma unroll
            for (int mi = 0; mi < 2; mi++){
                float4 av = Af[((wm*2 + mi)*4 + fk)*32 + lane];
                a[mi][0] = __float_as_uint(av.x); a[mi][1] = __float_as_uint(av.y);
                a[mi][2] = __float_as_uint(av.z); a[mi][3] = __float_as_uint(av.w);
            }
            const float2* Bf = Bbase + (size_t)k8g*8*32 + lane;
#pragma unroll
            for (int j = 0; j < 4; j++){
                float2 bv = __ldg(Bf + (wn*4 + j)*32);
                uint32_t b0 = __float_as_uint(bv.x), b1 = __float_as_uint(bv.y);
                mma8(acc[0][j], a[0][0],a[0][1],a[0][2],a[0][3], b0,b1);
                mma8(acc[1][j], a[1][0],a[1][1],a[1][2],a[1][3], b0,b1);
            }
        }
        if (ch < 53) store_stage((ch + 1) & 1);
        __syncthreads();
    }

    // exchange: bias + GELU -> smem in A-frag order (K=64)
    const int g4 = lane >> 2, t4 = lane & 3;
    float* A2 = &Abuf[0][0];
#pragma unroll
    for (int mi = 0; mi < 2; mi++){
        int fm = wm*2 + mi;
#pragma unroll
        for (int j = 0; j < 4; j++){
            int fn = wn*4 + j;
            float v[4] = {acc[mi][j].x, acc[mi][j].y, acc[mi][j].z, acc[mi][j].w};
#pragma unroll
            for (int q = 0; q < 4; q++){
                int hc = fn*8 + 2*t4 + (q & 1);
                int r2 = g4 + (q >> 1)*8;
                float x = v[q] + __ldg(bb1 + hc);
                float gl = 0.5f * x * (1.f + erff(x * 0.70710678118654752f));
                int l2  = g4*4 + (hc & 3);
                int pos = (r2 >> 3) + 2*((hc & 7) >> 2);
                A2[((fn*8 + fm)*32 + l2)*4 + pos] = to_tf32(gl);
            }
        }
    }
    __syncthreads();

    // 1x1 GEMM: K=64
    float4 acc2[2][4];
#pragma unroll
    for (int mi = 0; mi < 2; mi++)
#pragma unroll
        for (int j = 0; j < 4; j++) acc2[mi][j] = make_float4(0.f,0.f,0.f,0.f);

#pragma unroll
    for (int k8 = 0; k8 < 8; k8++){
        uint32_t a[2][4];
#pragma unroll
        for (int mi = 0; mi < 2; mi++){
            float4 av = *reinterpret_cast<const float4*>(
                &A2[((k8*8 + wm*2 + mi)*32 + lane)*4]);
            a[mi][0] = __float_as_uint(av.x); a[mi][1] = __float_as_uint(av.y);
            a[mi][2] = __float_as_uint(av.z); a[mi][3] = __float_as_uint(av.w);
        }
        const float2* Bf = reinterpret_cast<const float2*>(g_w2b) + (size_t)k8*8*32 + lane;
#pragma unroll
        for (int j = 0; j < 4; j++){
            float2 bv = __ldg(Bf + (wn*4 + j)*32);
            uint32_t b0 = __float_as_uint(bv.x), b1 = __float_as_uint(bv.y);
            mma8(acc2[0][j], a[0][0],a[0][1],a[0][2],a[0][3], b0,b1);
            mma8(acc2[1][j], a[1][0],a[1][1],a[1][2],a[1][3], b0,b1);
        }
    }

    // epilogue: bias + store
#pragma unroll
    for (int mi = 0; mi < 2; mi++){
        int fm = wm*2 + mi;
#pragma unroll
        for (int j = 0; j < 4; j++){
            int fn = wn*4 + j;
            float v[4] = {acc2[mi][j].x, acc2[mi][j].y, acc2[mi][j].z, acc2[mi][j].w};
#pragma unroll
            for (int q = 0; q < 4; q++){
                int oc = fn*8 + 2*t4 + (q & 1);
                int m  = fm*16 + g4 + (q >> 1)*8;
                int h  = hb*4 + (m >> 5);
                int wc = wb*32 + (m & 31);
                if (wc < BEV)
                    out[((size_t)b*BMID + oc)*BEVHW + h*BEV + wc] = v[q] + __ldg(bb2 + oc);
            }
        }
    }
}

// ======================================================================
extern "C" void kernel_launch(void* const* d_in, const int* in_sizes, int n_in,
                              void* d_out, int out_size)
{
    const float* feat   = (const float*)d_in[0];
    const float* dw1    = (const float*)d_in[1];
    const float* db1    = (const float*)d_in[2];
    const float* dgamma = (const float*)d_in[3];
    const float* dbeta  = (const float*)d_in[4];
    const float* dmean  = (const float*)d_in[5];
    const float* dvar   = (const float*)d_in[6];
    const float* dw2    = (const float*)d_in[7];
    const float* db2    = (const float*)d_in[8];
    const float* cw1    = (const float*)d_in[9];
    const float* cb1    = (const float*)d_in[10];
    const float* cgamma = (const float*)d_in[11];
    const float* cbeta  = (const float*)d_in[12];
    const float* cmean  = (const float*)d_in[13];
    const float* cvar   = (const float*)d_in[14];
    const float* cw2    = (const float*)d_in[15];
    const float* cb2    = (const float*)d_in[16];
    const float* bw1    = (const float*)d_in[17];
    const float* bb1    = (const float*)d_in[18];
    const float* bw2    = (const float*)d_in[19];
    const float* bb2    = (const float*)d_in[20];

    float* out = (float*)d_out;
    float* depth_logits = out + (long)NB*BMID*BEVHW;

    float *p_w1d, *p_w1c, *p_w1b, *p_w2d, *p_w2c, *p_w2b;
    cudaGetSymbolAddress((void**)&p_w1d, g_w1d);
    cudaGetSymbolAddress((void**)&p_w1c, g_w1c);
    cudaGetSymbolAddress((void**)&p_w1b, g_w1b);
    cudaGetSymbolAddress((void**)&p_w2d, g_w2d);
    cudaGetSymbolAddress((void**)&p_w2c, g_w2c);
    cudaGetSymbolAddress((void**)&p_w2b, g_w2b);

    prep_w1frag<<<(256*256*9 + 255)/256, 256>>>(dw1, p_w1d, 256, 256);
    prep_w1frag<<<(256*256*9 + 255)/256, 256>>>(cw1, p_w1c, 256, 256);
    prep_w1frag<<<(64*192*9 + 255)/256, 256>>>(bw1, p_w1b, 64, 192);
    prep_w2frag<<<(64*256 + 255)/256, 256>>>(dw2, p_w2d, DBINS, 256);
    prep_w2frag<<<(64*256 + 255)/256, 256>>>(cw2, p_w2c, CTXC, 256);
    prep_w2frag<<<(64*64 + 255)/256, 256>>>(bw2, p_w2b, 64, 64);

    // heads: conv3x3+BN+ReLU -> hidden frags; then 1x1 -> depth_logits / context
    // (softmax-sum over depth bins == 1, so pooled == context exactly)
    head3_mma<<<dim3(22, NCAM, 2), 512>>>(
        feat, db1, dgamma, dbeta, dmean, dvar,
              cb1, cgamma, cbeta, cmean, cvar);
    head1_mma<<<dim3(22, NCAM, 2), 256>>>(db2, cb2, depth_logits);

    // bilinear upsample (reshape is a pure view of g_context)
    {
        long total = (long)NB*BCIN*BEV*100;
        upsample_k<<<(int)((total + 255)/256), 256>>>();
    }

    // bev conv3x3 + GELU + 1x1, fused
    bev_mma<<<dim3(13, 100, NB), 256>>>(bb1, bb2, out);
}

// round 8
// speedup vs baseline: 2.8765x; 1.0915x over previous
#include <cuda_runtime.h>
#include <stdint.h>
#include <math.h>

#define NCAM 12
#define CIN 256
#define FH 32
#define FW 88
#define HW 2816
#define DBINS 41
#define CTXC 32
#define NB 2
#define BCIN 192
#define BEV 400
#define BMID 64
#define BEVHW 160000

// ---------------- scratch (device globals; no allocations) ----------------
__device__ __align__(16) float g_w1d[288*32*32*2];
__device__ __align__(16) float g_w1c[288*32*32*2];
__device__ __align__(16) float g_w1b[216*8*32*2];
__device__ __align__(16) float g_w2d[32*8*32*2];
__device__ __align__(16) float g_w2c[32*8*32*2];
__device__ __align__(16) float g_w2b[8*8*32*2];
__device__ __align__(16) float g_hidA[(size_t)2*NCAM*22*128*256];
__device__ __align__(16) float g_context[NCAM*CTXC*HW];
__device__ __align__(16) float g_bev[(size_t)NB*BCIN*BEVHW];
__device__ __align__(16) float g_featr[(size_t)NCAM*CIN*HW];   // tf32-rounded feat

// ---------------- helpers ----------------
__device__ __forceinline__ uint32_t f2tf32(float x){
    uint32_t r; asm("cvt.rna.tf32.f32 %0, %1;" : "=r"(r) : "f"(x)); return r;
}
__device__ __forceinline__ float to_tf32(float x){ return __uint_as_float(f2tf32(x)); }
__device__ __forceinline__ void mma8(float4& d,
    uint32_t a0, uint32_t a1, uint32_t a2, uint32_t a3,
    uint32_t b0, uint32_t b1)
{
    asm volatile("mma.sync.aligned.m16n8k8.row.col.f32.tf32.tf32.f32 "
        "{%0,%1,%2,%3}, {%4,%5,%6,%7}, {%8,%9}, {%0,%1,%2,%3};"
        : "+f"(d.x), "+f"(d.y), "+f"(d.z), "+f"(d.w)
        : "r"(a0), "r"(a1), "r"(a2), "r"(a3), "r"(b0), "r"(b1));
}

// ============ prep 1: the three conv3x3 weight arrays -> B-frag order ============
// k = t*IC + ic. out[((k8*NF+fn)*32 + l)*2 + pos], l=(oc&7)*4+(k&3), pos=(k&7)>>2
__global__ void prep_big(const float* __restrict__ dw1, const float* __restrict__ cw1,
                         const float* __restrict__ bw1)
{
    const int y = blockIdx.y;
    const float* w; float* o; int OC, IC;
    if (y == 0){ w = dw1; o = g_w1d; OC = 256; IC = 256; }
    else if (y == 1){ w = cw1; o = g_w1c; OC = 256; IC = 256; }
    else { w = bw1; o = g_w1b; OC = 64; IC = 192; }
    int idx = blockIdx.x*256 + threadIdx.x;
    if (idx >= OC*IC*9) return;
    int oc = idx / (IC*9);
    int rr = idx - oc*(IC*9);
    int ic = rr / 9;
    int t  = rr - ic*9;
    int k  = t*IC + ic;
    int NF = OC >> 3;
    int l = (oc & 7)*4 + (k & 3);
    int pos = (k & 7) >> 2;
    o[(((k>>3)*NF + (oc>>3))*32 + l)*2 + pos] = to_tf32(w[idx]);
}

// ============ prep 2: 1x1 weights -> frags (padded to 64) + feat rounding ============
__global__ void prep_small(const float* __restrict__ dw2, const float* __restrict__ cw2,
                           const float* __restrict__ bw2, const float* __restrict__ feat)
{
    const int y = blockIdx.y;
    if (y == 3){
        int i = blockIdx.x*256 + threadIdx.x;        // float4 index
        if (i < (NCAM*CIN*HW)/4){
            float4 v = __ldg(reinterpret_cast<const float4*>(feat) + i);
            v.x = to_tf32(v.x); v.y = to_tf32(v.y);
            v.z = to_tf32(v.z); v.w = to_tf32(v.w);
            reinterpret_cast<float4*>(g_featr)[i] = v;
        }
        return;
    }
    const float* w; float* o; int OC, K;
    if (y == 0){ w = dw2; o = g_w2d; OC = DBINS; K = 256; }
    else if (y == 1){ w = cw2; o = g_w2c; OC = CTXC; K = 256; }
    else { w = bw2; o = g_w2b; OC = 64; K = 64; }
    int idx = blockIdx.x*256 + threadIdx.x;
    if (idx >= 64*K) return;
    int oc = idx / K, k = idx - oc*K;
    float v = (oc < OC) ? to_tf32(w[(size_t)oc*K + k]) : 0.f;
    int l = (oc & 7)*4 + (k & 3);
    int pos = (k & 7) >> 2;
    o[(((k>>3)*8 + (oc>>3))*32 + l)*2 + pos] = v;
}

// ============ HEAD conv3x3 + BN + ReLU -> g_hidA (frag order) ============
// grid (22, 12, 2), 512 threads. M=128 px, N=256, K=2304 (72 chunks of 32).
__global__ __launch_bounds__(512) void head3_mma(
    const float* __restrict__ db1, const float* __restrict__ dg,
    const float* __restrict__ dbt, const float* __restrict__ dm, const float* __restrict__ dv,
    const float* __restrict__ cb1, const float* __restrict__ cg,
    const float* __restrict__ cbt, const float* __restrict__ cm, const float* __restrict__ cv)
{
    __shared__ __align__(16) float Abuf[2][4096];
    __shared__ float sS[256], sT[256];

    const int tid = threadIdx.x;
    const int pb = blockIdx.x, n = blockIdx.y, head = blockIdx.z;
    const float* W1 = head ? g_w1c : g_w1d;

    if (tid < 256){
        int c = tid;
        float gam = head ? cg[c]  : dg[c];
        float var = head ? cv[c]  : dv[c];
        float bet = head ? cbt[c] : dbt[c];
        float mu  = head ? cm[c]  : dm[c];
        float bi  = head ? cb1[c] : db1[c];
        float s = gam * rsqrtf(var + 1e-5f);
        sS[c] = s;
        sT[c] = bet + (bi - mu)*s;
    }

    const int lane = tid & 31;
    const int wrp  = tid >> 5;
    const int wm = wrp & 3;          // m-warp: fm = wm*2 + mi
    const int wn = wrp >> 2;         // n-warp: fn = wn*8 + j

    // staging precompute: 2 slots per thread, 9-bit tap-validity masks
    int sOff0[2], sOff1[2], sIc[2], sSlot[2];
    uint32_t mA[2], mB[2];
#pragma unroll
    for (int i = 0; i < 2; i++){
        int s = tid + i*512;
        int fm = s >> 7, fk = (s >> 5) & 3, l = s & 31;
        int m0 = fm*16 + (l >> 2);
        int px0 = pb*128 + m0, px1 = px0 + 8;
        int h0 = px0 / FW, w0 = px0 % FW;
        int h1 = px1 / FW, w1 = px1 % FW;
        sOff0[i] = px0; sOff1[i] = px1;
        sIc[i] = fk*8 + (l & 3);
        sSlot[i] = s;
        mA[i] = 0; mB[i] = 0;
#pragma unroll
        for (int t = 0; t < 9; t++){
            int dy = t/3 - 1, dx = t - (t/3)*3 - 1;
            if ((unsigned)(h0+dy) < FH && (unsigned)(w0+dx) < FW) mA[i] |= 1u << t;
            if ((unsigned)(h1+dy) < FH && (unsigned)(w1+dx) < FW) mB[i] |= 1u << t;
        }
    }

    float4 acc[2][8];
#pragma unroll
    for (int mi = 0; mi < 2; mi++)
#pragma unroll
        for (int j = 0; j < 8; j++) acc[mi][j] = make_float4(0.f,0.f,0.f,0.f);

    float pv[2][4];
    auto gather = [&](int ch){
        int t = ch >> 3, icb = ch & 7;
        int dy = t/3 - 1, dx = t - (t/3)*3 - 1;
        int doff = dy*FW + dx;
#pragma unroll
        for (int i = 0; i < 2; i++){
            const float* base = g_featr + ((size_t)n*CIN + icb*32 + sIc[i])*HW;
            bool ok0 = (mA[i] >> t) & 1;
            bool ok1 = (mB[i] >> t) & 1;
            int o0 = sOff0[i] + doff, o1 = sOff1[i] + doff;
            pv[i][0] = ok0 ? __ldg(base + o0) : 0.f;
            pv[i][1] = ok1 ? __ldg(base + o1) : 0.f;
            pv[i][2] = ok0 ? __ldg(base + 4*HW + o0) : 0.f;
            pv[i][3] = ok1 ? __ldg(base + 4*HW + o1) : 0.f;
        }
    };
    auto store_stage = [&](int buf){
#pragma unroll
        for (int i = 0; i < 2; i++)
            *reinterpret_cast<float4*>(&Abuf[buf][sSlot[i]*4]) =
                make_float4(pv[i][0], pv[i][1], pv[i][2], pv[i][3]);
    };

    gather(0);
    store_stage(0);
    __syncthreads();

    for (int ch = 0; ch < 72; ch++){
        if (ch < 71) gather(ch + 1);
        const float4* Af = reinterpret_cast<const float4*>(&Abuf[ch & 1][0]);
        const float2* Bbase = reinterpret_cast<const float2*>(W1);
#pragma unroll
        for (int fk = 0; fk < 4; fk++){
            int k8g = ch*4 + fk;
            uint32_t a[2][4];
#pragma unroll
            for (int mi = 0; mi < 2; mi++){
                float4 av = Af[((wm*2 + mi)*4 + fk)*32 + lane];
                a[mi][0] = __float_as_uint(av.x); a[mi][1] = __float_as_uint(av.y);
                a[mi][2] = __float_as_uint(av.z); a[mi][3] = __float_as_uint(av.w);
            }
            const float2* Bf = Bbase + (size_t)k8g*32*32 + lane;
#pragma unroll
            for (int j = 0; j < 8; j++){
                float2 bv = __ldg(Bf + (wn*8 + j)*32);
                uint32_t b0 = __float_as_uint(bv.x), b1 = __float_as_uint(bv.y);
                mma8(acc[0][j], a[0][0],a[0][1],a[0][2],a[0][3], b0,b1);
                mma8(acc[1][j], a[1][0],a[1][1],a[1][2],a[1][3], b0,b1);
            }
        }
        if (ch < 71) store_stage((ch + 1) & 1);
        __syncthreads();
    }

    // epilogue: BN + ReLU, write in stage-2 A-fragment order
    const int g4 = lane >> 2, t4 = lane & 3;
    float* dst = g_hidA + ((size_t)(head*NCAM + n)*22 + pb)*32768;
#pragma unroll
    for (int mi = 0; mi < 2; mi++){
        int fm = wm*2 + mi;
#pragma unroll
        for (int j = 0; j < 8; j++){
            int fn = wn*8 + j;
            float v[4] = {acc[mi][j].x, acc[mi][j].y, acc[mi][j].z, acc[mi][j].w};
#pragma unroll
            for (int q = 0; q < 4; q++){
                int oc = fn*8 + 2*t4 + (q & 1);
                int r2 = g4 + (q >> 1)*8;
                float val = fmaxf(fmaf(v[q], sS[oc], sT[oc]), 0.f);
                int l2  = g4*4 + (oc & 3);
                int pos = (r2 >> 3) + 2*((oc & 7) >> 2);
                dst[(size_t)((fn*8 + fm)*32 + l2)*4 + pos] = to_tf32(val);
            }
        }
    }
}

// ============ HEAD 1x1 (256 -> 41/32), reads g_hidA frags directly ============
__global__ __launch_bounds__(256) void head1_mma(
    const float* __restrict__ db2, const float* __restrict__ cb2,
    float* __restrict__ depth_out)
{
    const int tid = threadIdx.x;
    const int pb = blockIdx.x, n = blockIdx.y, head = blockIdx.z;
    const int lane = tid & 31, wrp = tid >> 5;
    const int wm = wrp & 3, wn = wrp >> 2;

    const float* W2 = head ? g_w2c : g_w2d;
    const float* Ab = g_hidA + ((size_t)(head*NCAM + n)*22 + pb)*32768;

    float4 acc[2][4];
#pragma unroll
    for (int mi = 0; mi < 2; mi++)
#pragma unroll
        for (int j = 0; j < 4; j++) acc[mi][j] = make_float4(0.f,0.f,0.f,0.f);

#pragma unroll 4
    for (int k8 = 0; k8 < 32; k8++){
        uint32_t a[2][4];
#pragma unroll
        for (int mi = 0; mi < 2; mi++){
            float4 av = __ldg(reinterpret_cast<const float4*>(Ab) +
                              (k8*8 + wm*2 + mi)*32 + lane);
            a[mi][0] = __float_as_uint(av.x); a[mi][1] = __float_as_uint(av.y);
            a[mi][2] = __float_as_uint(av.z); a[mi][3] = __float_as_uint(av.w);
        }
        const float2* Bf = reinterpret_cast<const float2*>(W2) + (size_t)k8*8*32 + lane;
#pragma unroll
        for (int j = 0; j < 4; j++){
            float2 bv = __ldg(Bf + (wn*4 + j)*32);
            uint32_t b0 = __float_as_uint(bv.x), b1 = __float_as_uint(bv.y);
            mma8(acc[0][j], a[0][0],a[0][1],a[0][2],a[0][3], b0,b1);
            mma8(acc[1][j], a[1][0],a[1][1],a[1][2],a[1][3], b0,b1);
        }
    }

    const int g4 = lane >> 2, t4 = lane & 3;
#pragma unroll
    for (int mi = 0; mi < 2; mi++){
        int fm = wm*2 + mi;
#pragma unroll
        for (int j = 0; j < 4; j++){
            int fn = wn*4 + j;
            float v[4] = {acc[mi][j].x, acc[mi][j].y, acc[mi][j].z, acc[mi][j].w};
#pragma unroll
            for (int q = 0; q < 4; q++){
                int oc = fn*8 + 2*t4 + (q & 1);
                int px = pb*128 + fm*16 + g4 + (q >> 1)*8;
                if (head == 0){
                    if (oc < DBINS)
                        depth_out[((size_t)n*DBINS + oc)*HW + px] = v[q] + __ldg(db2 + oc);
                } else {
                    if (oc < CTXC)
                        g_context[((size_t)n*CTXC + oc)*HW + px] = v[q] + __ldg(cb2 + oc);
                }
            }
        }
    }
}

// ============ bilinear upsample (half-pixel, clamp), writes tf32-rounded ============
__global__ __launch_bounds__(256) void upsample_k()
{
    long idx = (long)blockIdx.x * 256 + threadIdx.x;
    const long total = (long)NB*BCIN*BEV*100;
    if (idx >= total) return;
    int q = (int)(idx % 100);
    long rr = idx / 100;
    int i = (int)(rr % BEV);  rr /= BEV;
    int g = (int)(rr % BCIN);
    int b = (int)(rr / BCIN);

    float sy = (i + 0.5f) * (32.f/400.f) - 0.5f;
    int y0 = (int)floorf(sy); float fy = sy - (float)y0;
    int y1 = y0 + 1;
    y0 = max(0, min(FH-1, y0)); y1 = max(0, min(FH-1, y1));
    const float* p0 = g_context + ((long)b*BCIN + g)*HW + y0*FW;
    const float* p1 = g_context + ((long)b*BCIN + g)*HW + y1*FW;

    float4 o; float* ov = &o.x;
#pragma unroll
    for (int c = 0; c < 4; c++){
        int j = q*4 + c;
        float sx = (j + 0.5f) * (88.f/400.f) - 0.5f;
        int x0 = (int)floorf(sx); float fx = sx - (float)x0;
        int x1 = x0 + 1;
        x0 = max(0, min(FW-1, x0)); x1 = max(0, min(FW-1, x1));
        float t  = p0[x0] + (p0[x1] - p0[x0]) * fx;
        float bo = p1[x0] + (p1[x1] - p1[x0]) * fx;
        ov[c] = to_tf32(t + (bo - t) * fy);
    }
    *reinterpret_cast<float4*>(&g_bev[(((long)b*BCIN + g)*BEV + i)*BEV + q*4]) = o;
}

// ============ BEV conv3x3 + GELU + 1x1, fused mma ============
// grid (13, 50, 2), 512 threads. Tile = 8 rows x 32 cols = 256 px. N=64, K=1728.
// dynamic smem: 16384 floats (2 stage buffers of 8192; A2 exchange overlays both)
__global__ __launch_bounds__(512) void bev_mma(
    const float* __restrict__ bb1, const float* __restrict__ bb2,
    float* __restrict__ out)
{
    extern __shared__ __align__(16) float sbuf[];
    float* Ast0 = sbuf;
    float* Ast1 = sbuf + 8192;

    const int tid = threadIdx.x;
    const int wb = blockIdx.x, hb = blockIdx.y, b = blockIdx.z;
    const int lane = tid & 31, wrp = tid >> 5;
    const int wm = wrp & 3;          // m-warp: fm = wm*4 + mi (mi 0..3)
    const int wn = wrp >> 2;         // n-warp 0..3: fn = wn*2 + j (j 0..1)

    // staging precompute: 4 slots per thread (2048 slots total)
    int sO0[4], sO1[4], sC[4], sSlot[4];
    uint32_t mA[4], mB[4];
#pragma unroll
    for (int i = 0; i < 4; i++){
        int s = tid + i*512;
        int fm = s >> 7, fk = (s >> 5) & 3, l = s & 31;
        int m0 = fm*16 + (l >> 2), m1 = m0 + 8;
        int h0 = hb*8 + (m0 >> 5), w0 = wb*32 + (m0 & 31);
        int h1 = hb*8 + (m1 >> 5), w1 = wb*32 + (m1 & 31);
        sO0[i] = h0*BEV + w0; sO1[i] = h1*BEV + w1;
        sC[i] = (fk*8 + (l & 3))*BEVHW;
        sSlot[i] = s;
        mA[i] = 0; mB[i] = 0;
#pragma unroll
        for (int t = 0; t < 9; t++){
            int dy = t/3 - 1, dx = t - (t/3)*3 - 1;
            if ((unsigned)(h0+dy) < BEV && (unsigned)(w0+dx) < BEV) mA[i] |= 1u << t;
            if ((unsigned)(h1+dy) < BEV && (unsigned)(w1+dx) < BEV) mB[i] |= 1u << t;
        }
    }

    float4 acc[4][2];
#pragma unroll
    for (int mi = 0; mi < 4; mi++)
#pragma unroll
        for (int j = 0; j < 2; j++) acc[mi][j] = make_float4(0.f,0.f,0.f,0.f);

    float pv[4][4];
    auto gather = [&](int ch){
        int t = ch / 6, icb = ch - t*6;
        int dy = t/3 - 1, dx = t - (t/3)*3 - 1;
        int doff = dy*BEV + dx;
        const float* chbase = g_bev + ((size_t)b*BCIN + icb*32)*BEVHW;
#pragma unroll
        for (int i = 0; i < 4; i++){
            const float* base = chbase + sC[i];
            bool ok0 = (mA[i] >> t) & 1;
            bool ok1 = (mB[i] >> t) & 1;
            int o0 = sO0[i] + doff, o1 = sO1[i] + doff;
            pv[i][0] = ok0 ? __ldg(base + o0) : 0.f;
            pv[i][1] = ok1 ? __ldg(base + o1) : 0.f;
            pv[i][2] = ok0 ? __ldg(base + 4*BEVHW + o0) : 0.f;
            pv[i][3] = ok1 ? __ldg(base + 4*BEVHW + o1) : 0.f;
        }
    };
    auto store_stage = [&](float* buf){
#pragma unroll
        for (int i = 0; i < 4; i++)
            *reinterpret_cast<float4*>(&buf[sSlot[i]*4]) =
                make_float4(pv[i][0], pv[i][1], pv[i][2], pv[i][3]);
    };

    gather(0);
    store_stage(Ast0);
    __syncthreads();

    for (int ch = 0; ch < 54; ch++){
        if (ch < 53) gather(ch + 1);
        const float4* Af = reinterpret_cast<const float4*>((ch & 1) ? Ast1 : Ast0);
        const float2* Bbase = reinterpret_cast<const float2*>(g_w1b);
#pragma unroll
        for (int fk = 0; fk < 4; fk++){
            int k8g = ch*4 + fk;
            uint32_t a[4][4];
#pragma unroll
            for (int mi = 0; mi < 4; mi++){
                float4 av = Af[((wm*4 + mi)*4 + fk)*32 + lane];
                a[mi][0] = __float_as_uint(av.x); a[mi][1] = __float_as_uint(av.y);
                a[mi][2] = __float_as_uint(av.z); a[mi][3] = __float_as_uint(av.w);
            }
            const float2* Bf = Bbase + (size_t)k8g*8*32 + lane;
#pragma unroll
            for (int j = 0; j < 2; j++){
                float2 bv = __ldg(Bf + (wn*2 + j)*32);
                uint32_t b0 = __float_as_uint(bv.x), b1 = __float_as_uint(bv.y);
#pragma unroll
                for (int mi = 0; mi < 4; mi++)
                    mma8(acc[mi][j], a[mi][0],a[mi][1],a[mi][2],a[mi][3], b0,b1);
            }
        }
        if (ch < 53) store_stage(((ch + 1) & 1) ? Ast1 : Ast0);
        __syncthreads();
    }

    // exchange: bias + GELU -> smem in A-frag order (K=64, M=256; overlays both buffers)
    const int g4 = lane >> 2, t4 = lane & 3;
    float* A2 = sbuf;
#pragma unroll
    for (int mi = 0; mi < 4; mi++){
        int fm = wm*4 + mi;
#pragma unroll
        for (int j = 0; j < 2; j++){
            int fn = wn*2 + j;
            float v[4] = {acc[mi][j].x, acc[mi][j].y, acc[mi][j].z, acc[mi][j].w};
#pragma unroll
            for (int q = 0; q < 4; q++){
                int hc = fn*8 + 2*t4 + (q & 1);
                int r2 = g4 + (q >> 1)*8;
                float x = v[q] + __ldg(bb1 + hc);
                float gl = 0.5f * x * (1.f + erff(x * 0.70710678118654752f));
                int l2  = g4*4 + (hc & 3);
                int pos = (r2 >> 3) + 2*((hc & 7) >> 2);
                A2[((fn*16 + fm)*32 + l2)*4 + pos] = to_tf32(gl);
            }
        }
    }
    __syncthreads();

    // 1x1 GEMM: K=64
    float4 acc2[4][2];
#pragma unroll
    for (int mi = 0; mi < 4; mi++)
#pragma unroll
        for (int j = 0; j < 2; j++) acc2[mi][j] = make_float4(0.f,0.f,0.f,0.f);

#pragma unroll
    for (int k8 = 0; k8 < 8; k8++){
        uint32_t a[4][4];
#pragma unroll
        for (int mi = 0; mi < 4; mi++){
            float4 av = reinterpret_cast<const float4*>(A2)[(k8*16 + wm*4 + mi)*32 + lane];
            a[mi][0] = __float_as_uint(av.x); a[mi][1] = __float_as_uint(av.y);
            a[mi][2] = __float_as_uint(av.z); a[mi][3] = __float_as_uint(av.w);
        }
        const float2* Bf = reinterpret_cast<const float2*>(g_w2b) + (size_t)k8*8*32 + lane;
#pragma unroll
        for (int j = 0; j < 2; j++){
            float2 bv = __ldg(Bf + (wn*2 + j)*32);
            uint32_t b0 = __float_as_uint(bv.x), b1 = __float_as_uint(bv.y);
#pragma unroll
            for (int mi = 0; mi < 4; mi++)
                mma8(acc2[mi][j], a[mi][0],a[mi][1],a[mi][2],a[mi][3], b0,b1);
        }
    }

    // epilogue: bias + store
#pragma unroll
    for (int mi = 0; mi < 4; mi++){
        int fm = wm*4 + mi;
#pragma unroll
        for (int j = 0; j < 2; j++){
            int fn = wn*2 + j;
            float v[4] = {acc2[mi][j].x, acc2[mi][j].y, acc2[mi][j].z, acc2[mi][j].w};
#pragma unroll
            for (int q = 0; q < 4; q++){
                int oc = fn*8 + 2*t4 + (q & 1);
                int m  = fm*16 + g4 + (q >> 1)*8;
                int h  = hb*8 + (m >> 5);
                int wc = wb*32 + (m & 31);
                if (wc < BEV)
                    out[((size_t)b*BMID + oc)*BEVHW + h*BEV + wc] = v[q] + __ldg(bb2 + oc);
            }
        }
    }
}

// ======================================================================
extern "C" void kernel_launch(void* const* d_in, const int* in_sizes, int n_in,
                              void* d_out, int out_size)
{
    const float* feat   = (const float*)d_in[0];
    const float* dw1    = (const float*)d_in[1];
    const float* db1    = (const float*)d_in[2];
    const float* dgamma = (const float*)d_in[3];
    const float* dbeta  = (const float*)d_in[4];
    const float* dmean  = (const float*)d_in[5];
    const float* dvar   = (const float*)d_in[6];
    const float* dw2    = (const float*)d_in[7];
    const float* db2    = (const float*)d_in[8];
    const float* cw1    = (const float*)d_in[9];
    const float* cb1    = (const float*)d_in[10];
    const float* cgamma = (const float*)d_in[11];
    const float* cbeta  = (const float*)d_in[12];
    const float* cmean  = (const float*)d_in[13];
    const float* cvar   = (const float*)d_in[14];
    const float* cw2    = (const float*)d_in[15];
    const float* cb2    = (const float*)d_in[16];
    const float* bw1    = (const float*)d_in[17];
    const float* bb1    = (const float*)d_in[18];
    const float* bw2    = (const float*)d_in[19];
    const float* bb2    = (const float*)d_in[20];

    float* out = (float*)d_out;
    float* depth_logits = out + (long)NB*BMID*BEVHW;

    cudaFuncSetAttribute(bev_mma, cudaFuncAttributeMaxDynamicSharedMemorySize, 65536);

    // launch order keeps bev_mma at index 5 so ncu (-s 5 -c 1) profiles it
    prep_big<<<dim3(2304, 3), 256>>>(dw1, cw1, bw1);
    prep_small<<<dim3((NCAM*CIN*HW/4 + 255)/256, 4), 256>>>(dw2, cw2, bw2, feat);

    // heads (softmax-sum over depth bins == 1, so pooled == context exactly)
    head3_mma<<<dim3(22, NCAM, 2), 512>>>(
        db1, dgamma, dbeta, dmean, dvar,
        cb1, cgamma, cbeta, cmean, cvar);
    head1_mma<<<dim3(22, NCAM, 2), 256>>>(db2, cb2, depth_logits);

    {
        long total = (long)NB*BCIN*BEV*100;
        upsample_k<<<(int)((total + 255)/256), 256>>>();
    }

    bev_mma<<<dim3(13, 50, NB), 512, 65536>>>(bb1, bb2, out);
}